// round 16
// baseline (speedup 1.0000x reference)
#include <cuda_runtime.h>
#include <cuda_bf16.h>
#include <math.h>
#include <stdint.h>

// ---------------- problem constants ----------------
#define BB    2
#define QQ    300
#define TSEQ  25
#define CDIM  256
#define NHEADS 8
#define HDIM  32
#define NL    4
#define NP    4
#define DFF   1024
#define LQTOT 7500
#define NTOK  15000
#define NSEQ  600
#define SVAL  21760

// ---------------- fp32 scratch ----------------
__device__ __align__(16) float g_ln1[NTOK * CDIM];
__device__ __align__(16) float g_offaw[NTOK * 384];
__device__ __align__(16) float g_ln2[NTOK * CDIM];
__device__ __align__(16) float g_bias384[384];

// ---------------- bf16 scratch ----------------
__device__ __align__(16) __nv_bfloat16 gb_qk[NTOK * 512];
__device__ __align__(16) __nv_bfloat16 gb_v[NTOK * CDIM];
__device__ __align__(16) __nv_bfloat16 gb_value[(size_t)BB * SVAL * CDIM];
__device__ __align__(16) __nv_bfloat16 gb_tgt[NTOK * CDIM];
__device__ __align__(16) __nv_bfloat16 gb_qksum[NTOK * CDIM];
__device__ __align__(16) __nv_bfloat16 gb_attn[NTOK * CDIM];
__device__ __align__(16) __nv_bfloat16 gb_query[NTOK * CDIM];
__device__ __align__(16) __nv_bfloat16 gb_src[(size_t)BB * SVAL * CDIM];
__device__ __align__(16) __nv_bfloat16 gb_accum[NTOK * CDIM];
__device__ __align__(16) __nv_bfloat16 gb_ln2[NTOK * CDIM];
__device__ __align__(16) __nv_bfloat16 gb_ffn1[NTOK * DFF];
// weights
__device__ __align__(16) __nv_bfloat16 gb_inproj[768 * 256];
__device__ __align__(16) __nv_bfloat16 gb_outproj[256 * 256];
__device__ __align__(16) __nv_bfloat16 gb_soffaw[384 * 256];
__device__ __align__(16) __nv_bfloat16 gb_vp[256 * 256];
__device__ __align__(16) __nv_bfloat16 gb_op[256 * 256];
__device__ __align__(16) __nv_bfloat16 gb_f1w[1024 * 256];
__device__ __align__(16) __nv_bfloat16 gb_f2w[256 * 1024];

// ================= helpers =================
__device__ __forceinline__ uint32_t smem_to_u32(const void* p) {
    uint32_t a;
    asm("{ .reg .u64 t; cvta.to.shared.u64 t, %1; cvt.u32.u64 %0, t; }" : "=r"(a) : "l"(p));
    return a;
}
__device__ __forceinline__ void cpasync16(uint32_t dst, const void* src) {
    asm volatile("cp.async.ca.shared.global [%0], [%1], 16;" :: "r"(dst), "l"(src) : "memory");
}
#define CP_COMMIT() asm volatile("cp.async.commit_group;" ::: "memory")

__device__ __forceinline__ void ldmatrix_x4(uint32_t& r0, uint32_t& r1, uint32_t& r2,
                                            uint32_t& r3, uint32_t addr) {
    asm volatile("ldmatrix.sync.aligned.m8n8.x4.shared.b16 {%0,%1,%2,%3}, [%4];"
                 : "=r"(r0), "=r"(r1), "=r"(r2), "=r"(r3) : "r"(addr));
}
__device__ __forceinline__ void mma_bf16(float* d, const uint32_t* a, uint32_t b0, uint32_t b1) {
    asm volatile(
        "mma.sync.aligned.m16n8k16.row.col.f32.bf16.bf16.f32 "
        "{%0,%1,%2,%3}, {%4,%5,%6,%7}, {%8,%9}, {%0,%1,%2,%3};"
        : "+f"(d[0]), "+f"(d[1]), "+f"(d[2]), "+f"(d[3])
        : "r"(a[0]), "r"(a[1]), "r"(a[2]), "r"(a[3]), "r"(b0), "r"(b1));
}
__device__ __forceinline__ uint32_t pack_bf16(float x, float y) {
    uint32_t r;
    asm("cvt.rn.bf16x2.f32 %0, %1, %2;" : "=r"(r) : "f"(y), "f"(x));
    return r;
}
__device__ __forceinline__ float bf_lo(uint32_t u) { return __uint_as_float(u << 16); }
__device__ __forceinline__ float bf_hi(uint32_t u) { return __uint_as_float(u & 0xFFFF0000u); }

// ================= bf16 mma.sync GEMM (general) =================
// Block tile 128x128, 8 warps (4Mx2N), warp tile 32x64, 3-stage pipeline.
#define GEMM_SMEM (3 * 32768)

template <int K>
__device__ __forceinline__ void fill_chunk_b(uint32_t sbuf,
                                             const __nv_bfloat16* __restrict__ A,
                                             const __nv_bfloat16* __restrict__ B,
                                             int bm, int bn, int M, int k0, int tid) {
    const int which = tid >> 7;
    const int t = tid & 127;
    const int g = t & 7;
    const int r0 = t >> 3;
    const uint32_t dbase = sbuf + (uint32_t)(which * 16384);
#pragma unroll
    for (int j = 0; j < 8; j++) {
        const int r = r0 + j * 16;
        int gr;
        if (which) {
            gr = bn + r;
        } else {
            gr = bm + r; if (gr >= M) gr = M - 1;
        }
        const __nv_bfloat16* gp = (which ? B : A) + (size_t)gr * K + k0 + g * 8;
        const uint32_t d = dbase + (uint32_t)(r * 128) + (uint32_t)(((g ^ (r & 7)) << 4));
        cpasync16(d, gp);
    }
}

template <int EPI, int OUTBF, int NC>
__global__ __launch_bounds__(256, 2) void gemm_mma(
        const __nv_bfloat16* __restrict__ A, const __nv_bfloat16* __restrict__ B,
        const float* __restrict__ bias, const float* __restrict__ res,
        void* __restrict__ Cout, int M, int N) {
    constexpr int K = NC * 64;
    extern __shared__ char smem[];
    const uint32_t smem_u = smem_to_u32(smem);
    const int tid = threadIdx.x;
    const int wid = tid >> 5;
    const int lane = tid & 31;
    const int wm = wid & 3;
    const int wn = wid >> 2;
    const int bm = blockIdx.y * 128;
    const int bn = blockIdx.x * 128;

    float acc[2][8][4];
#pragma unroll
    for (int mt = 0; mt < 2; mt++)
#pragma unroll
        for (int nt = 0; nt < 8; nt++)
#pragma unroll
            for (int e = 0; e < 4; e++) acc[mt][nt][e] = 0.f;

    fill_chunk_b<K>(smem_u, A, B, bm, bn, M, 0, tid);
    CP_COMMIT();
    fill_chunk_b<K>(smem_u + 32768, A, B, bm, bn, M, 64, tid);
    CP_COMMIT();

    const uint32_t laneRowOff = (uint32_t)((((lane & 7) + ((lane >> 3) & 1) * 8)) * 128);
    const int xr = lane & 7;
    const int gsel = lane >> 4;
    uint32_t swz[4];
#pragma unroll
    for (int ks = 0; ks < 4; ks++)
        swz[ks] = (uint32_t)(((ks * 2 + gsel) ^ xr) << 4);

    const uint32_t aBase0 = (uint32_t)((wm * 32) * 128) + laneRowOff;
    const uint32_t aBase1 = aBase0 + 16 * 128;
    uint32_t bBase[4];
#pragma unroll
    for (int j = 0; j < 4; j++)
        bBase[j] = 16384u + (uint32_t)((wn * 64 + j * 16) * 128) + laneRowOff;

#pragma unroll
    for (int i = 0; i < NC; i++) {
        asm volatile("cp.async.wait_group 1;" ::: "memory");
        __syncthreads();

        const uint32_t buf = smem_u + (uint32_t)((i % 3) * 32768);

#pragma unroll
        for (int ks = 0; ks < 4; ks++) {
            const uint32_t s = swz[ks];
            uint32_t Af[2][4];
            ldmatrix_x4(Af[0][0], Af[0][1], Af[0][2], Af[0][3], buf + aBase0 + s);
            ldmatrix_x4(Af[1][0], Af[1][1], Af[1][2], Af[1][3], buf + aBase1 + s);
            uint32_t Bf[4][4];
#pragma unroll
            for (int j = 0; j < 4; j++)
                ldmatrix_x4(Bf[j][0], Bf[j][1], Bf[j][2], Bf[j][3], buf + bBase[j] + s);
#pragma unroll
            for (int mt = 0; mt < 2; mt++)
#pragma unroll
                for (int j = 0; j < 4; j++) {
                    mma_bf16(acc[mt][j * 2 + 0], Af[mt], Bf[j][0], Bf[j][2]);
                    mma_bf16(acc[mt][j * 2 + 1], Af[mt], Bf[j][1], Bf[j][3]);
                }
        }

        if (i + 2 < NC) {
            fill_chunk_b<K>(smem_u + (uint32_t)(((i + 2) % 3) * 32768), A, B, bm, bn, M,
                            (i + 2) * 64, tid);
        }
        CP_COMMIT();
    }

    const int q = lane >> 2;
    const int ccol = bn + wn * 64;
    const float* biasp = bias + ccol;
    const int t2 = (lane & 3) * 2;
#pragma unroll
    for (int mt = 0; mt < 2; mt++) {
#pragma unroll
        for (int rs = 0; rs < 2; rs++) {
            const int r = bm + wm * 32 + mt * 16 + q + rs * 8;
            if (r >= M) continue;
            const float* rp = (EPI == 2) ? res + (size_t)r * N + ccol : nullptr;
#pragma unroll
            for (int nt = 0; nt < 8; nt++) {
                const int c = nt * 8 + t2;
                float vx = acc[mt][nt][rs * 2 + 0] + biasp[c];
                float vy = acc[mt][nt][rs * 2 + 1] + biasp[c + 1];
                if (EPI == 1) { vx = fmaxf(vx, 0.f); vy = fmaxf(vy, 0.f); }
                if (EPI == 2) { vx += rp[c]; vy += rp[c + 1]; }
                if (OUTBF) {
                    uint32_t* cp = (uint32_t*)((__nv_bfloat16*)Cout + (size_t)r * N + ccol + c);
                    *cp = pack_bf16(vx, vy);
                } else {
                    float* cp = (float*)Cout + (size_t)r * N + ccol + c;
                    *(float2*)cp = make_float2(vx, vy);
                }
            }
        }
    }
}

// ================= GEMM with fused residual + LayerNorm (N == 256) ==========
// Block tile 64 rows x 256 cols (full rows), 256 threads = 8 warps (2M x 4N),
// warp tile 32x64, 2-stage pipeline (40 KB/stage, 80 KB total), 2 blocks/SM.
// LNV: 1 -> bout=bf16(out+pos), 2 -> bout=bf16(out), 3 -> no bout.
#define GEMM_LN_SMEM (2 * 40960)

template <int K>
__device__ __forceinline__ void fill_ln(uint32_t sbuf,
                                        const __nv_bfloat16* __restrict__ A,
                                        const __nv_bfloat16* __restrict__ B,
                                        int bm, int M, int k0, int tid) {
    const int g = tid & 7;
    const int r0 = tid >> 3;     // 0..31
#pragma unroll
    for (int j = 0; j < 2; j++) {      // A: 64 rows
        const int r = r0 + j * 32;
        int gr = bm + r; if (gr >= M) gr = M - 1;
        cpasync16(sbuf + (uint32_t)(r * 128) + (uint32_t)((g ^ (r & 7)) << 4),
                  A + (size_t)gr * K + k0 + g * 8);
    }
#pragma unroll
    for (int j = 0; j < 8; j++) {      // B: 256 rows
        const int r = r0 + j * 32;
        cpasync16(sbuf + 8192u + (uint32_t)(r * 128) + (uint32_t)((g ^ (r & 7)) << 4),
                  B + (size_t)r * K + k0 + g * 8);
    }
}

template <int LNV, int NC>
__global__ __launch_bounds__(256, 2) void gemm_ln(
        const __nv_bfloat16* __restrict__ A, const __nv_bfloat16* __restrict__ B,
        const float* __restrict__ bias, const float* __restrict__ res,
        const float* __restrict__ gam, const float* __restrict__ bet,
        const float* __restrict__ pos,
        float* __restrict__ yout, __nv_bfloat16* __restrict__ bout, int M) {
    constexpr int K = NC * 64;
    extern __shared__ char smem[];
    const uint32_t smem_u = smem_to_u32(smem);
    const int tid = threadIdx.x;
    const int wid = tid >> 5;
    const int lane = tid & 31;
    const int wm = wid & 1;            // 2 warps in M, 32 rows each
    const int wn = wid >> 1;           // 4 warps in N, 64 cols each
    const int bm = blockIdx.x * 64;

    float acc[2][8][4];
#pragma unroll
    for (int mt = 0; mt < 2; mt++)
#pragma unroll
        for (int nt = 0; nt < 8; nt++)
#pragma unroll
            for (int e = 0; e < 4; e++) acc[mt][nt][e] = 0.f;

    fill_ln<K>(smem_u, A, B, bm, M, 0, tid);
    CP_COMMIT();
    fill_ln<K>(smem_u + 40960, A, B, bm, M, 64, tid);
    CP_COMMIT();

    const uint32_t laneRowOff = (uint32_t)((((lane & 7) + ((lane >> 3) & 1) * 8)) * 128);
    const int xr = lane & 7;
    const int gsel = lane >> 4;
    uint32_t swz[4];
#pragma unroll
    for (int ks = 0; ks < 4; ks++)
        swz[ks] = (uint32_t)(((ks * 2 + gsel) ^ xr) << 4);

    const uint32_t aBase0 = (uint32_t)((wm * 32) * 128) + laneRowOff;
    const uint32_t aBase1 = aBase0 + 16 * 128;
    uint32_t bBase[4];
#pragma unroll
    for (int j = 0; j < 4; j++)
        bBase[j] = 8192u + (uint32_t)((wn * 64 + j * 16) * 128) + laneRowOff;

#pragma unroll
    for (int i = 0; i < NC; i++) {
        asm volatile("cp.async.wait_group 1;" ::: "memory");
        __syncthreads();

        const uint32_t buf = smem_u + (uint32_t)((i & 1) * 40960);

#pragma unroll
        for (int ks = 0; ks < 4; ks++) {
            const uint32_t s = swz[ks];
            uint32_t Af[2][4];
            ldmatrix_x4(Af[0][0], Af[0][1], Af[0][2], Af[0][3], buf + aBase0 + s);
            ldmatrix_x4(Af[1][0], Af[1][1], Af[1][2], Af[1][3], buf + aBase1 + s);
            uint32_t Bf[4][4];
#pragma unroll
            for (int j = 0; j < 4; j++)
                ldmatrix_x4(Bf[j][0], Bf[j][1], Bf[j][2], Bf[j][3], buf + bBase[j] + s);
#pragma unroll
            for (int mt = 0; mt < 2; mt++)
#pragma unroll
                for (int j = 0; j < 4; j++) {
                    mma_bf16(acc[mt][j * 2 + 0], Af[mt], Bf[j][0], Bf[j][2]);
                    mma_bf16(acc[mt][j * 2 + 1], Af[mt], Bf[j][1], Bf[j][3]);
                }
        }
        __syncthreads();   // all reads of stage (i&1) done before refill

        if (i + 2 < NC) {
            fill_ln<K>(smem_u + (uint32_t)((i & 1) * 40960), A, B, bm, M, (i + 2) * 64, tid);
        }
        CP_COMMIT();
    }

    // ---- epilogue: bias + residual, then LayerNorm across the 256-wide row ----
    const int q = lane >> 2;
    const int t2 = (lane & 3) * 2;
    float* redp = (float*)smem;  // [64 rows][4 wn][2] = 2 KB

#pragma unroll
    for (int mt = 0; mt < 2; mt++) {
#pragma unroll
        for (int rs = 0; rs < 2; rs++) {
            const int rloc = wm * 32 + mt * 16 + q + rs * 8;
            int r = bm + rloc; if (r >= M) r = M - 1;
            const float* rrow = res + (size_t)r * 256 + wn * 64;
            float s = 0.f, s2 = 0.f;
#pragma unroll
            for (int nt = 0; nt < 8; nt++) {
                const int c = nt * 8 + t2;
                const int col = wn * 64 + c;
                float vx = acc[mt][nt][rs * 2 + 0] + bias[col] + rrow[c];
                float vy = acc[mt][nt][rs * 2 + 1] + bias[col + 1] + rrow[c + 1];
                acc[mt][nt][rs * 2 + 0] = vx;
                acc[mt][nt][rs * 2 + 1] = vy;
                s += vx + vy;
                s2 += vx * vx + vy * vy;
            }
            s  += __shfl_xor_sync(~0u, s, 1);  s  += __shfl_xor_sync(~0u, s, 2);
            s2 += __shfl_xor_sync(~0u, s2, 1); s2 += __shfl_xor_sync(~0u, s2, 2);
            if ((lane & 3) == 0) {
                redp[(rloc * 4 + wn) * 2 + 0] = s;
                redp[(rloc * 4 + wn) * 2 + 1] = s2;
            }
        }
    }
    __syncthreads();

#pragma unroll
    for (int mt = 0; mt < 2; mt++) {
#pragma unroll
        for (int rs = 0; rs < 2; rs++) {
            const int rloc = wm * 32 + mt * 16 + q + rs * 8;
            const int r = bm + rloc;
            if (r >= M) continue;
            float ts = 0.f, ts2 = 0.f;
#pragma unroll
            for (int w4 = 0; w4 < 4; w4++) {
                ts  += redp[(rloc * 4 + w4) * 2 + 0];
                ts2 += redp[(rloc * 4 + w4) * 2 + 1];
            }
            const float mean = ts * (1.f / 256.f);
            const float var = ts2 * (1.f / 256.f) - mean * mean;
            const float rstd = rsqrtf(var + 1e-5f);
            float* yrow = yout + (size_t)r * 256;
            const float* prow = (LNV == 1) ? pos + (size_t)r * 256 : nullptr;
#pragma unroll
            for (int nt = 0; nt < 8; nt++) {
                const int col = wn * 64 + nt * 8 + t2;
                float o0 = (acc[mt][nt][rs * 2 + 0] - mean) * rstd * gam[col] + bet[col];
                float o1 = (acc[mt][nt][rs * 2 + 1] - mean) * rstd * gam[col + 1] + bet[col + 1];
                *(float2*)(yrow + col) = make_float2(o0, o1);
                if (LNV == 1) {
                    uint32_t* bp = (uint32_t*)(bout + (size_t)r * 256 + col);
                    *bp = pack_bf16(o0 + prow[col], o1 + prow[col + 1]);
                } else if (LNV == 2) {
                    uint32_t* bp = (uint32_t*)(bout + (size_t)r * 256 + col);
                    *bp = pack_bf16(o0, o1);
                }
            }
        }
    }
}

// ---------------- fused weight convert + bias concat ------------
struct WConvArgs {
    const float4* in[8];
    uint2* out[8];
    int off4[9];
    const float4* sob4;
    const float4* awb4;
    float4* bias384;
};
__global__ void wconv_kernel(WConvArgs a) {
    int i = blockIdx.x * blockDim.x + threadIdx.x;
    if (i < 96) {
        a.bias384[i] = (i < 64) ? a.sob4[i] : a.awb4[i - 64];
    }
    if (i >= a.off4[8]) return;
    int s = 0;
#pragma unroll
    for (int k = 1; k < 8; k++) s += (i >= a.off4[k]);
    int j = i - a.off4[s];
    float4 v = a.in[s][j];
    uint2 o;
    o.x = pack_bf16(v.x, v.y);
    o.y = pack_bf16(v.z, v.w);
    a.out[s][j] = o;
}

// ---------------- fp32 -> bf16 convert ----------------
__global__ void f2b_kernel(const float* __restrict__ in, __nv_bfloat16* __restrict__ out, int n4) {
    int i = blockIdx.x * blockDim.x + threadIdx.x;
    if (i < n4) {
        float4 v = ((const float4*)in)[i];
        uint2 o;
        o.x = pack_bf16(v.x, v.y);
        o.y = pack_bf16(v.z, v.w);
        ((uint2*)out)[i] = o;
    }
}

// ---------------- fused: qksum = bf16(tgt+pos), tgtb = bf16(tgt) ----------
__global__ void prep_kernel(const float* __restrict__ tgt, const float* __restrict__ pos,
                            __nv_bfloat16* __restrict__ qksum, __nv_bfloat16* __restrict__ tgtb,
                            int n4) {
    int i = blockIdx.x * blockDim.x + threadIdx.x;
    if (i < n4) {
        float4 x = ((const float4*)tgt)[i];
        float4 y = ((const float4*)pos)[i];
        uint2 t;
        t.x = pack_bf16(x.x, x.y);
        t.y = pack_bf16(x.z, x.w);
        ((uint2*)tgtb)[i] = t;
        uint2 o;
        o.x = pack_bf16(x.x + y.x, x.y + y.y);
        o.y = pack_bf16(x.z + y.z, x.w + y.w);
        ((uint2*)qksum)[i] = o;
    }
}

// ---------------- self-attention (lane = query), reduced registers ----------
__global__ __launch_bounds__(128, 5) void attn_kernel(
        const __nv_bfloat16* __restrict__ qk, const __nv_bfloat16* __restrict__ v,
        __nv_bfloat16* __restrict__ out) {
    const int seq  = blockIdx.x >> 1;
    const int w    = threadIdx.x >> 5;
    const int h    = ((blockIdx.x & 1) << 2) + w;
    const int lane = threadIdx.x & 31;

    __shared__ float Ks[4][25][32];
    __shared__ float Vs[4][25][32];
    __shared__ float Os[4][25][36];

    const size_t tokbase = (size_t)seq * TSEQ;
    for (int i = lane; i < TSEQ * 32; i += 32) {
        int r = i >> 5;
        Ks[w][r][lane] = __bfloat162float(qk[(tokbase + r) * 512 + 256 + h * 32 + lane]);
        Vs[w][r][lane] = __bfloat162float(v[(tokbase + r) * 256 + h * 32 + lane]);
    }
    __syncwarp();

    if (lane < TSEQ) {
        const uint4* qp = (const uint4*)(qk + (tokbase + lane) * 512 + h * 32);
        float p[25];
#pragma unroll
        for (int j = 0; j < TSEQ; j++) p[j] = 0.f;

        // loop-swapped: only an 8-float q chunk live at a time
#pragma unroll
        for (int ic = 0; ic < 4; ic++) {
            uint4 u = qp[ic];
            float qc[8];
            qc[0] = bf_lo(u.x); qc[1] = bf_hi(u.x);
            qc[2] = bf_lo(u.y); qc[3] = bf_hi(u.y);
            qc[4] = bf_lo(u.z); qc[5] = bf_hi(u.z);
            qc[6] = bf_lo(u.w); qc[7] = bf_hi(u.w);
#pragma unroll
            for (int j = 0; j < TSEQ; j++) {
                const float* kp = &Ks[w][j][ic * 8];
                float a = p[j];
#pragma unroll
                for (int i = 0; i < 8; i++) a = fmaf(qc[i], kp[i], a);
                p[j] = a;
            }
        }

        const float scale = 0.1767766952966369f;
        float m = -1e30f;
#pragma unroll
        for (int j = 0; j < TSEQ; j++) { p[j] *= scale; m = fmaxf(m, p[j]); }
        float sum = 0.f;
#pragma unroll
        for (int j = 0; j < TSEQ; j++) { p[j] = __expf(p[j] - m); sum += p[j]; }
        const float inv = 1.f / sum;
#pragma unroll
        for (int d4 = 0; d4 < 8; d4++) {
            float4 o = make_float4(0.f, 0.f, 0.f, 0.f);
#pragma unroll
            for (int j = 0; j < TSEQ; j++) {
                float4 v4 = ((const float4*)Vs[w][j])[d4];
                o.x = fmaf(p[j], v4.x, o.x); o.y = fmaf(p[j], v4.y, o.y);
                o.z = fmaf(p[j], v4.z, o.z); o.w = fmaf(p[j], v4.w, o.w);
            }
            float* orow = &Os[w][lane][d4 * 4];
            orow[0] = o.x * inv; orow[1] = o.y * inv;
            orow[2] = o.z * inv; orow[3] = o.w * inv;
        }
    }
    __syncwarp();
    for (int i = lane; i < TSEQ * 32; i += 32) {
        int r = i >> 5;
        out[(tokbase + r) * 256 + h * 32 + lane] = __float2bfloat16(Os[w][r][lane]);
    }
}

// ---------------- deformable sampling w/ fused aw softmax, bf16 value -------
__global__ __launch_bounds__(256) void deform_kernel(
        const float* __restrict__ ref,
        const int* __restrict__ shapes,
        const int* __restrict__ lstart,
        __nv_bfloat16* __restrict__ out) {
    const int token = blockIdx.x;
    const int h = threadIdx.x >> 5;
    const int lane = threadIdx.x & 31;
    const int b = token / LQTOT;
    const int lq = token - b * LQTOT;

    __shared__ float sAw[8][16];

    {
        float v = -1e30f;
        if (lane < 16) v = g_offaw[(size_t)token * 384 + 256 + h * 16 + lane];
        float m = v;
#pragma unroll
        for (int o = 8; o; o >>= 1) m = fmaxf(m, __shfl_xor_sync(~0u, m, o, 16));
        float e = (lane < 16) ? __expf(v - m) : 0.f;
        float s = e;
#pragma unroll
        for (int o = 8; o; o >>= 1) s += __shfl_xor_sync(~0u, s, o, 16);
        if (lane < 16) sAw[h][lane] = e / s;
    }
    __syncwarp();

    const float* offp = g_offaw + (size_t)token * 384 + h * 32;
    const float* awp  = sAw[h];
    const float* refp = ref + ((size_t)(b * LQTOT + lq) * NL) * 2;
    const size_t vbase = ((size_t)b * SVAL) * 256;

    float acc = 0.f;
#pragma unroll
    for (int l = 0; l < NL; l++) {
        const int Hl = shapes[l * 2];
        const int Wl = shapes[l * 2 + 1];
        const int st = lstart[l];
        const float rx = refp[l * 2];
        const float ry = refp[l * 2 + 1];
        const float fW = (float)Wl, fH = (float)Hl;
#pragma unroll
        for (int p = 0; p < 4; p++) {
            float ox = offp[l * 8 + p * 2];
            float oy = offp[l * 8 + p * 2 + 1];
            float aww = awp[l * 4 + p];
            float x = (rx + ox / fW) * fW - 0.5f;
            float y = (ry + oy / fH) * fH - 0.5f;
            float fx0 = floorf(x), fy0 = floorf(y);
            float wx = x - fx0, wy = y - fy0;
            int x0 = (int)fx0, y0 = (int)fy0;
            float tw[4] = {(1.f - wx) * (1.f - wy), wx * (1.f - wy),
                           (1.f - wx) * wy, wx * wy};
            int xs[4] = {x0, x0 + 1, x0, x0 + 1};
            int ys[4] = {y0, y0, y0 + 1, y0 + 1};
#pragma unroll
            for (int tgt = 0; tgt < 4; tgt++) {
                int xi = xs[tgt], yi = ys[tgt];
                if (xi >= 0 && xi < Wl && yi >= 0 && yi < Hl) {
                    size_t vi = vbase + ((size_t)(st + yi * Wl + xi)) * 256 + h * 32 + lane;
                    acc = fmaf(__bfloat162float(gb_value[vi]), tw[tgt] * aww, acc);
                }
            }
        }
    }
    out[(size_t)token * 256 + h * 32 + lane] = __float2bfloat16(acc);
}

// ---------------- launch ----------------
static void* sym(const void* s) {
    void* p = nullptr;
    cudaGetSymbolAddress(&p, s);
    return p;
}

template <int EPI, int OUTBF, int NC>
static void launch_gemm(const __nv_bfloat16* A, const __nv_bfloat16* B, const float* bias,
                        const float* res, void* C, int M, int N, cudaStream_t st) {
    static bool done = false;
    if (!done) {
        cudaFuncSetAttribute(gemm_mma<EPI, OUTBF, NC>, cudaFuncAttributeMaxDynamicSharedMemorySize, GEMM_SMEM);
        done = true;
    }
    dim3 grid(N / 128, (M + 127) / 128);
    gemm_mma<EPI, OUTBF, NC><<<grid, 256, GEMM_SMEM, st>>>(A, B, bias, res, C, M, N);
}

template <int LNV, int NC>
static void launch_gemm_ln(const __nv_bfloat16* A, const __nv_bfloat16* B, const float* bias,
                           const float* res, const float* gam, const float* bet,
                           const float* pos, float* yout, __nv_bfloat16* bout, int M) {
    static bool done = false;
    if (!done) {
        cudaFuncSetAttribute(gemm_ln<LNV, NC>, cudaFuncAttributeMaxDynamicSharedMemorySize, GEMM_LN_SMEM);
        done = true;
    }
    gemm_ln<LNV, NC><<<(M + 63) / 64, 256, GEMM_LN_SMEM>>>(A, B, bias, res, gam, bet, pos, yout, bout, M);
}

extern "C" void kernel_launch(void* const* d_in, const int* in_sizes, int n_in,
                              void* d_out, int out_size) {
    const float* tgt  = (const float*)d_in[0];
    const float* pos  = (const float*)d_in[1];
    const float* ref  = (const float*)d_in[2];
    const float* src  = (const float*)d_in[3];
    const int* shapes = (const int*)d_in[4];
    const int* lstart = (const int*)d_in[5];
    const float* in_proj_w  = (const float*)d_in[6];
    const float* in_proj_b  = (const float*)d_in[7];
    const float* out_proj_w = (const float*)d_in[8];
    const float* out_proj_b = (const float*)d_in[9];
    const float* ln1_g = (const float*)d_in[10];
    const float* ln1_b = (const float*)d_in[11];
    const float* samp_off_w = (const float*)d_in[12];
    const float* samp_off_b = (const float*)d_in[13];
    const float* aw_w = (const float*)d_in[14];
    const float* aw_b = (const float*)d_in[15];
    const float* vp_w = (const float*)d_in[16];
    const float* vp_b = (const float*)d_in[17];
    const float* op_w = (const float*)d_in[18];
    const float* op_b = (const float*)d_in[19];
    const float* ln2_g = (const float*)d_in[20];
    const float* ln2_b = (const float*)d_in[21];
    const float* ffn1_w = (const float*)d_in[22];
    const float* ffn1_b = (const float*)d_in[23];
    const float* ffn2_w = (const float*)d_in[24];
    const float* ffn2_b = (const float*)d_in[25];
    const float* ln3_g = (const float*)d_in[26];
    const float* ln3_b = (const float*)d_in[27];

    float* p_ln1   = (float*)sym(g_ln1);
    float* p_offaw = (float*)sym(g_offaw);
    float* p_ln2   = (float*)sym(g_ln2);
    float* p_b384  = (float*)sym(g_bias384);

    __nv_bfloat16* b_qk    = (__nv_bfloat16*)sym(gb_qk);
    __nv_bfloat16* b_v     = (__nv_bfloat16*)sym(gb_v);
    __nv_bfloat16* b_value = (__nv_bfloat16*)sym(gb_value);
    __nv_bfloat16* b_tgt   = (__nv_bfloat16*)sym(gb_tgt);
    __nv_bfloat16* b_qksum = (__nv_bfloat16*)sym(gb_qksum);
    __nv_bfloat16* b_attn  = (__nv_bfloat16*)sym(gb_attn);
    __nv_bfloat16* b_query = (__nv_bfloat16*)sym(gb_query);
    __nv_bfloat16* b_src   = (__nv_bfloat16*)sym(gb_src);
    __nv_bfloat16* b_accum = (__nv_bfloat16*)sym(gb_accum);
    __nv_bfloat16* b_ln2   = (__nv_bfloat16*)sym(gb_ln2);
    __nv_bfloat16* b_ffn1  = (__nv_bfloat16*)sym(gb_ffn1);
    __nv_bfloat16* b_inproj = (__nv_bfloat16*)sym(gb_inproj);
    __nv_bfloat16* b_outproj = (__nv_bfloat16*)sym(gb_outproj);
    __nv_bfloat16* b_soffaw = (__nv_bfloat16*)sym(gb_soffaw);
    __nv_bfloat16* b_vp    = (__nv_bfloat16*)sym(gb_vp);
    __nv_bfloat16* b_op    = (__nv_bfloat16*)sym(gb_op);
    __nv_bfloat16* b_f1w   = (__nv_bfloat16*)sym(gb_f1w);
    __nv_bfloat16* b_f2w   = (__nv_bfloat16*)sym(gb_f2w);

    static cudaStream_t s2 = nullptr, s3 = nullptr;
    static cudaEvent_t evRoot = nullptr, evW = nullptr, evPrep = nullptr, evV = nullptr, evVp = nullptr;
    if (!s2) {
        cudaStreamCreateWithFlags(&s2, cudaStreamNonBlocking);
        cudaStreamCreateWithFlags(&s3, cudaStreamNonBlocking);
        cudaEventCreateWithFlags(&evRoot, cudaEventDisableTiming);
        cudaEventCreateWithFlags(&evW, cudaEventDisableTiming);
        cudaEventCreateWithFlags(&evPrep, cudaEventDisableTiming);
        cudaEventCreateWithFlags(&evV, cudaEventDisableTiming);
        cudaEventCreateWithFlags(&evVp, cudaEventDisableTiming);
    }

    // Fork side streams from the capturing stream.
    cudaEventRecord(evRoot, 0);
    cudaStreamWaitEvent(s2, evRoot, 0);
    cudaStreamWaitEvent(s3, evRoot, 0);

    // s2: weight converts + bias concat
    {
        WConvArgs a;
        const float* ins[8] = {in_proj_w, out_proj_w, samp_off_w, aw_w, vp_w, op_w, ffn1_w, ffn2_w};
        __nv_bfloat16* outs[8] = {b_inproj, b_outproj, b_soffaw, b_soffaw + 256 * 256,
                                  b_vp, b_op, b_f1w, b_f2w};
        int ns[8] = {768 * 256, 256 * 256, 256 * 256, 128 * 256, 256 * 256, 256 * 256, 1024 * 256, 256 * 1024};
        int acc4 = 0;
        for (int i = 0; i < 8; i++) {
            a.in[i] = (const float4*)ins[i];
            a.out[i] = (uint2*)outs[i];
            a.off4[i] = acc4;
            acc4 += ns[i] / 4;
        }
        a.off4[8] = acc4;
        a.sob4 = (const float4*)samp_off_b;
        a.awb4 = (const float4*)aw_b;
        a.bias384 = (float4*)p_b384;
        wconv_kernel<<<(acc4 + 255) / 256, 256, 0, s2>>>(a);
        cudaEventRecord(evW, s2);
    }
    // main: prep (tgt+pos)
    const int n4 = NTOK * CDIM / 4;
    prep_kernel<<<(n4 + 255) / 256, 256>>>(tgt, pos, b_qksum, b_tgt, n4);
    cudaEventRecord(evPrep, 0);
    // s3: src convert
    const int s4 = BB * SVAL * CDIM / 4;
    f2b_kernel<<<(s4 + 255) / 256, 256, 0, s3>>>(src, b_src, s4);

    // main: qk GEMM
    cudaStreamWaitEvent(0, evW, 0);
    launch_gemm<0, 1, 4>(b_qksum, b_inproj, in_proj_b, nullptr, b_qk, NTOK, 512, 0);

    // s2: v GEMM
    cudaStreamWaitEvent(s2, evPrep, 0);
    launch_gemm<0, 1, 4>(b_tgt, b_inproj + 512 * 256, in_proj_b + 512, nullptr, b_v, NTOK, 256, s2);
    cudaEventRecord(evV, s2);

    // s3: vp GEMM
    cudaStreamWaitEvent(s3, evW, 0);
    launch_gemm<0, 1, 4>(b_src, b_vp, vp_b, nullptr, b_value, BB * SVAL, 256, s3);
    cudaEventRecord(evVp, s3);

    cudaStreamWaitEvent(0, evV, 0);
    attn_kernel<<<NSEQ * 2, 128>>>(b_qk, b_v, b_attn);

    // outproj + residual(tgt) + LN1 fused (emits ln1 fp32 + query bf16 = ln1+pos)
    launch_gemm_ln<1, 4>(b_attn, b_outproj, out_proj_b, tgt, ln1_g, ln1_b, pos,
                         p_ln1, b_query, NTOK);

    launch_gemm<0, 0, 4>(b_query, b_soffaw, p_b384, nullptr, p_offaw, NTOK, 384, 0);

    cudaStreamWaitEvent(0, evVp, 0);
    deform_kernel<<<NTOK, 256>>>(ref, shapes, lstart, b_accum);

    // op + residual(ln1) + LN2 fused (emits ln2 fp32 + ln2 bf16)
    launch_gemm_ln<2, 4>(b_accum, b_op, op_b, p_ln1, ln2_g, ln2_b, nullptr,
                         p_ln2, b_ln2, NTOK);

    launch_gemm<1, 1, 4>(b_ln2, b_f1w, ffn1_b, nullptr, b_ffn1, NTOK, DFF, 0);

    // ffn2 + residual(ln2) + LN3 fused -> final output
    launch_gemm_ln<3, 16>(b_ffn1, b_f2w, ffn2_b, p_ln2, ln3_g, ln3_b, nullptr,
                          (float*)d_out, nullptr, NTOK);
}

// round 17
// speedup vs baseline: 1.0046x; 1.0046x over previous
#include <cuda_runtime.h>
#include <cuda_bf16.h>
#include <math.h>
#include <stdint.h>

// ---------------- problem constants ----------------
#define BB    2
#define QQ    300
#define TSEQ  25
#define CDIM  256
#define NHEADS 8
#define HDIM  32
#define NL    4
#define NP    4
#define DFF   1024
#define LQTOT 7500
#define NTOK  15000
#define NSEQ  600
#define SVAL  21760

// ---------------- fp32 scratch ----------------
__device__ __align__(16) float g_ln1[NTOK * CDIM];
__device__ __align__(16) float g_offaw[NTOK * 384];
__device__ __align__(16) float g_ln2[NTOK * CDIM];
__device__ __align__(16) float g_bias384[384];

// ---------------- bf16 scratch ----------------
__device__ __align__(16) __nv_bfloat16 gb_qk[NTOK * 512];
__device__ __align__(16) __nv_bfloat16 gb_v[NTOK * CDIM];
__device__ __align__(16) __nv_bfloat16 gb_value[(size_t)BB * SVAL * CDIM];
__device__ __align__(16) __nv_bfloat16 gb_tgt[NTOK * CDIM];
__device__ __align__(16) __nv_bfloat16 gb_qksum[NTOK * CDIM];
__device__ __align__(16) __nv_bfloat16 gb_attn[NTOK * CDIM];
__device__ __align__(16) __nv_bfloat16 gb_query[NTOK * CDIM];
__device__ __align__(16) __nv_bfloat16 gb_src[(size_t)BB * SVAL * CDIM];
__device__ __align__(16) __nv_bfloat16 gb_accum[NTOK * CDIM];
__device__ __align__(16) __nv_bfloat16 gb_ln2[NTOK * CDIM];
__device__ __align__(16) __nv_bfloat16 gb_ffn1[NTOK * DFF];
// weights
__device__ __align__(16) __nv_bfloat16 gb_inproj[768 * 256];
__device__ __align__(16) __nv_bfloat16 gb_outproj[256 * 256];
__device__ __align__(16) __nv_bfloat16 gb_soffaw[384 * 256];
__device__ __align__(16) __nv_bfloat16 gb_vp[256 * 256];
__device__ __align__(16) __nv_bfloat16 gb_op[256 * 256];
__device__ __align__(16) __nv_bfloat16 gb_f1w[1024 * 256];
__device__ __align__(16) __nv_bfloat16 gb_f2w[256 * 1024];

// ================= helpers =================
__device__ __forceinline__ uint32_t smem_to_u32(const void* p) {
    uint32_t a;
    asm("{ .reg .u64 t; cvta.to.shared.u64 t, %1; cvt.u32.u64 %0, t; }" : "=r"(a) : "l"(p));
    return a;
}
__device__ __forceinline__ void cpasync16(uint32_t dst, const void* src) {
    asm volatile("cp.async.ca.shared.global [%0], [%1], 16;" :: "r"(dst), "l"(src) : "memory");
}
#define CP_COMMIT() asm volatile("cp.async.commit_group;" ::: "memory")

__device__ __forceinline__ void ldmatrix_x4(uint32_t& r0, uint32_t& r1, uint32_t& r2,
                                            uint32_t& r3, uint32_t addr) {
    asm volatile("ldmatrix.sync.aligned.m8n8.x4.shared.b16 {%0,%1,%2,%3}, [%4];"
                 : "=r"(r0), "=r"(r1), "=r"(r2), "=r"(r3) : "r"(addr));
}
__device__ __forceinline__ void mma_bf16(float* d, const uint32_t* a, uint32_t b0, uint32_t b1) {
    asm volatile(
        "mma.sync.aligned.m16n8k16.row.col.f32.bf16.bf16.f32 "
        "{%0,%1,%2,%3}, {%4,%5,%6,%7}, {%8,%9}, {%0,%1,%2,%3};"
        : "+f"(d[0]), "+f"(d[1]), "+f"(d[2]), "+f"(d[3])
        : "r"(a[0]), "r"(a[1]), "r"(a[2]), "r"(a[3]), "r"(b0), "r"(b1));
}
__device__ __forceinline__ uint32_t pack_bf16(float x, float y) {
    uint32_t r;
    asm("cvt.rn.bf16x2.f32 %0, %1, %2;" : "=r"(r) : "f"(y), "f"(x));
    return r;
}
__device__ __forceinline__ float bf_lo(uint32_t u) { return __uint_as_float(u << 16); }
__device__ __forceinline__ float bf_hi(uint32_t u) { return __uint_as_float(u & 0xFFFF0000u); }

// ================= bf16 mma.sync GEMM (general) =================
// Block tile 128x128, 8 warps (4Mx2N), warp tile 32x64, 3-stage pipeline.
#define GEMM_SMEM (3 * 32768)

template <int K>
__device__ __forceinline__ void fill_chunk_b(uint32_t sbuf,
                                             const __nv_bfloat16* __restrict__ A,
                                             const __nv_bfloat16* __restrict__ B,
                                             int bm, int bn, int M, int k0, int tid) {
    const int which = tid >> 7;
    const int t = tid & 127;
    const int g = t & 7;
    const int r0 = t >> 3;
    const uint32_t dbase = sbuf + (uint32_t)(which * 16384);
#pragma unroll
    for (int j = 0; j < 8; j++) {
        const int r = r0 + j * 16;
        int gr;
        if (which) {
            gr = bn + r;
        } else {
            gr = bm + r; if (gr >= M) gr = M - 1;
        }
        const __nv_bfloat16* gp = (which ? B : A) + (size_t)gr * K + k0 + g * 8;
        const uint32_t d = dbase + (uint32_t)(r * 128) + (uint32_t)(((g ^ (r & 7)) << 4));
        cpasync16(d, gp);
    }
}

template <int EPI, int OUTBF, int NC>
__global__ __launch_bounds__(256, 2) void gemm_mma(
        const __nv_bfloat16* __restrict__ A, const __nv_bfloat16* __restrict__ B,
        const float* __restrict__ bias, const float* __restrict__ res,
        void* __restrict__ Cout, int M, int N) {
    constexpr int K = NC * 64;
    extern __shared__ char smem[];
    const uint32_t smem_u = smem_to_u32(smem);
    const int tid = threadIdx.x;
    const int wid = tid >> 5;
    const int lane = tid & 31;
    const int wm = wid & 3;
    const int wn = wid >> 2;
    const int bm = blockIdx.y * 128;
    const int bn = blockIdx.x * 128;

    float acc[2][8][4];
#pragma unroll
    for (int mt = 0; mt < 2; mt++)
#pragma unroll
        for (int nt = 0; nt < 8; nt++)
#pragma unroll
            for (int e = 0; e < 4; e++) acc[mt][nt][e] = 0.f;

    fill_chunk_b<K>(smem_u, A, B, bm, bn, M, 0, tid);
    CP_COMMIT();
    fill_chunk_b<K>(smem_u + 32768, A, B, bm, bn, M, 64, tid);
    CP_COMMIT();

    const uint32_t laneRowOff = (uint32_t)((((lane & 7) + ((lane >> 3) & 1) * 8)) * 128);
    const int xr = lane & 7;
    const int gsel = lane >> 4;
    uint32_t swz[4];
#pragma unroll
    for (int ks = 0; ks < 4; ks++)
        swz[ks] = (uint32_t)(((ks * 2 + gsel) ^ xr) << 4);

    const uint32_t aBase0 = (uint32_t)((wm * 32) * 128) + laneRowOff;
    const uint32_t aBase1 = aBase0 + 16 * 128;
    uint32_t bBase[4];
#pragma unroll
    for (int j = 0; j < 4; j++)
        bBase[j] = 16384u + (uint32_t)((wn * 64 + j * 16) * 128) + laneRowOff;

#pragma unroll
    for (int i = 0; i < NC; i++) {
        asm volatile("cp.async.wait_group 1;" ::: "memory");
        __syncthreads();

        const uint32_t buf = smem_u + (uint32_t)((i % 3) * 32768);

#pragma unroll
        for (int ks = 0; ks < 4; ks++) {
            const uint32_t s = swz[ks];
            uint32_t Af[2][4];
            ldmatrix_x4(Af[0][0], Af[0][1], Af[0][2], Af[0][3], buf + aBase0 + s);
            ldmatrix_x4(Af[1][0], Af[1][1], Af[1][2], Af[1][3], buf + aBase1 + s);
            uint32_t Bf[4][4];
#pragma unroll
            for (int j = 0; j < 4; j++)
                ldmatrix_x4(Bf[j][0], Bf[j][1], Bf[j][2], Bf[j][3], buf + bBase[j] + s);
#pragma unroll
            for (int mt = 0; mt < 2; mt++)
#pragma unroll
                for (int j = 0; j < 4; j++) {
                    mma_bf16(acc[mt][j * 2 + 0], Af[mt], Bf[j][0], Bf[j][2]);
                    mma_bf16(acc[mt][j * 2 + 1], Af[mt], Bf[j][1], Bf[j][3]);
                }
        }

        if (i + 2 < NC) {
            fill_chunk_b<K>(smem_u + (uint32_t)(((i + 2) % 3) * 32768), A, B, bm, bn, M,
                            (i + 2) * 64, tid);
        }
        CP_COMMIT();
    }

    const int q = lane >> 2;
    const int ccol = bn + wn * 64;
    const float* biasp = bias + ccol;
    const int t2 = (lane & 3) * 2;
#pragma unroll
    for (int mt = 0; mt < 2; mt++) {
#pragma unroll
        for (int rs = 0; rs < 2; rs++) {
            const int r = bm + wm * 32 + mt * 16 + q + rs * 8;
            if (r >= M) continue;
            const float* rp = (EPI == 2) ? res + (size_t)r * N + ccol : nullptr;
#pragma unroll
            for (int nt = 0; nt < 8; nt++) {
                const int c = nt * 8 + t2;
                float vx = acc[mt][nt][rs * 2 + 0] + biasp[c];
                float vy = acc[mt][nt][rs * 2 + 1] + biasp[c + 1];
                if (EPI == 1) { vx = fmaxf(vx, 0.f); vy = fmaxf(vy, 0.f); }
                if (EPI == 2) { vx += rp[c]; vy += rp[c + 1]; }
                if (OUTBF) {
                    uint32_t* cp = (uint32_t*)((__nv_bfloat16*)Cout + (size_t)r * N + ccol + c);
                    *cp = pack_bf16(vx, vy);
                } else {
                    float* cp = (float*)Cout + (size_t)r * N + ccol + c;
                    *(float2*)cp = make_float2(vx, vy);
                }
            }
        }
    }
}

// ================= GEMM with fused residual + LayerNorm (N == 256) ==========
// Block tile 128 rows x 256 cols (full rows), 512 threads = 16 warps (4M x 4N),
// warp tile 32x64, 3-stage pipeline (48 KB/stage, 144 KB total), 1 block/SM.
// LNV: 1 -> bout=bf16(out+pos), 2 -> bout=bf16(out), 3 -> no bout.
#define GEMM_LN_SMEM (3 * 49152)

template <int K>
__device__ __forceinline__ void fill_ln(uint32_t sbuf,
                                        const __nv_bfloat16* __restrict__ A,
                                        const __nv_bfloat16* __restrict__ B,
                                        int bm, int M, int k0, int tid) {
    const int g = tid & 7;
    const int r0 = tid >> 3;     // 0..63
#pragma unroll
    for (int j = 0; j < 2; j++) {      // A: 128 rows
        const int r = r0 + j * 64;
        int gr = bm + r; if (gr >= M) gr = M - 1;
        cpasync16(sbuf + (uint32_t)(r * 128) + (uint32_t)((g ^ (r & 7)) << 4),
                  A + (size_t)gr * K + k0 + g * 8);
    }
#pragma unroll
    for (int j = 0; j < 4; j++) {      // B: 256 rows
        const int r = r0 + j * 64;
        cpasync16(sbuf + 16384u + (uint32_t)(r * 128) + (uint32_t)((g ^ (r & 7)) << 4),
                  B + (size_t)r * K + k0 + g * 8);
    }
}

template <int LNV, int NC>
__global__ __launch_bounds__(512, 1) void gemm_ln(
        const __nv_bfloat16* __restrict__ A, const __nv_bfloat16* __restrict__ B,
        const float* __restrict__ bias, const float* __restrict__ res,
        const float* __restrict__ gam, const float* __restrict__ bet,
        const float* __restrict__ pos,
        float* __restrict__ yout, __nv_bfloat16* __restrict__ bout, int M) {
    constexpr int K = NC * 64;
    extern __shared__ char smem[];
    const uint32_t smem_u = smem_to_u32(smem);
    const int tid = threadIdx.x;
    const int wid = tid >> 5;
    const int lane = tid & 31;
    const int wm = wid & 3;            // 4 warps in M, 32 rows each
    const int wn = wid >> 2;           // 4 warps in N, 64 cols each
    const int bm = blockIdx.x * 128;

    float acc[2][8][4];
#pragma unroll
    for (int mt = 0; mt < 2; mt++)
#pragma unroll
        for (int nt = 0; nt < 8; nt++)
#pragma unroll
            for (int e = 0; e < 4; e++) acc[mt][nt][e] = 0.f;

    fill_ln<K>(smem_u, A, B, bm, M, 0, tid);
    CP_COMMIT();
    fill_ln<K>(smem_u + 49152, A, B, bm, M, 64, tid);
    CP_COMMIT();

    const uint32_t laneRowOff = (uint32_t)((((lane & 7) + ((lane >> 3) & 1) * 8)) * 128);
    const int xr = lane & 7;
    const int gsel = lane >> 4;
    uint32_t swz[4];
#pragma unroll
    for (int ks = 0; ks < 4; ks++)
        swz[ks] = (uint32_t)(((ks * 2 + gsel) ^ xr) << 4);

    const uint32_t aBase0 = (uint32_t)((wm * 32) * 128) + laneRowOff;
    const uint32_t aBase1 = aBase0 + 16 * 128;
    uint32_t bBase[4];
#pragma unroll
    for (int j = 0; j < 4; j++)
        bBase[j] = 16384u + (uint32_t)((wn * 64 + j * 16) * 128) + laneRowOff;

#pragma unroll
    for (int i = 0; i < NC; i++) {
        asm volatile("cp.async.wait_group 1;" ::: "memory");
        __syncthreads();

        const uint32_t buf = smem_u + (uint32_t)((i % 3) * 49152);

#pragma unroll
        for (int ks = 0; ks < 4; ks++) {
            const uint32_t s = swz[ks];
            uint32_t Af[2][4];
            ldmatrix_x4(Af[0][0], Af[0][1], Af[0][2], Af[0][3], buf + aBase0 + s);
            ldmatrix_x4(Af[1][0], Af[1][1], Af[1][2], Af[1][3], buf + aBase1 + s);
            uint32_t Bf[4][4];
#pragma unroll
            for (int j = 0; j < 4; j++)
                ldmatrix_x4(Bf[j][0], Bf[j][1], Bf[j][2], Bf[j][3], buf + bBase[j] + s);
#pragma unroll
            for (int mt = 0; mt < 2; mt++)
#pragma unroll
                for (int j = 0; j < 4; j++) {
                    mma_bf16(acc[mt][j * 2 + 0], Af[mt], Bf[j][0], Bf[j][2]);
                    mma_bf16(acc[mt][j * 2 + 1], Af[mt], Bf[j][1], Bf[j][3]);
                }
        }

        if (i + 2 < NC) {
            fill_ln<K>(smem_u + (uint32_t)(((i + 2) % 3) * 49152), A, B, bm, M, (i + 2) * 64, tid);
        }
        CP_COMMIT();
    }

    // ---- epilogue: bias + residual, then LayerNorm across the 256-wide row ----
    __syncthreads();   // ensure smem free for reduction scratch
    const int q = lane >> 2;
    const int t2 = (lane & 3) * 2;
    float* redp = (float*)smem;  // [128 rows][4 wn][2] = 4 KB

#pragma unroll
    for (int mt = 0; mt < 2; mt++) {
#pragma unroll
        for (int rs = 0; rs < 2; rs++) {
            const int rloc = wm * 32 + mt * 16 + q + rs * 8;
            int r = bm + rloc; if (r >= M) r = M - 1;
            const float* rrow = res + (size_t)r * 256 + wn * 64;
            float s = 0.f, s2 = 0.f;
#pragma unroll
            for (int nt = 0; nt < 8; nt++) {
                const int c = nt * 8 + t2;
                const int col = wn * 64 + c;
                float vx = acc[mt][nt][rs * 2 + 0] + bias[col] + rrow[c];
                float vy = acc[mt][nt][rs * 2 + 1] + bias[col + 1] + rrow[c + 1];
                acc[mt][nt][rs * 2 + 0] = vx;
                acc[mt][nt][rs * 2 + 1] = vy;
                s += vx + vy;
                s2 += vx * vx + vy * vy;
            }
            s  += __shfl_xor_sync(~0u, s, 1);  s  += __shfl_xor_sync(~0u, s, 2);
            s2 += __shfl_xor_sync(~0u, s2, 1); s2 += __shfl_xor_sync(~0u, s2, 2);
            if ((lane & 3) == 0) {
                redp[(rloc * 4 + wn) * 2 + 0] = s;
                redp[(rloc * 4 + wn) * 2 + 1] = s2;
            }
        }
    }
    __syncthreads();

#pragma unroll
    for (int mt = 0; mt < 2; mt++) {
#pragma unroll
        for (int rs = 0; rs < 2; rs++) {
            const int rloc = wm * 32 + mt * 16 + q + rs * 8;
            const int r = bm + rloc;
            if (r >= M) continue;
            float ts = 0.f, ts2 = 0.f;
#pragma unroll
            for (int w4 = 0; w4 < 4; w4++) {
                ts  += redp[(rloc * 4 + w4) * 2 + 0];
                ts2 += redp[(rloc * 4 + w4) * 2 + 1];
            }
            const float mean = ts * (1.f / 256.f);
            const float var = ts2 * (1.f / 256.f) - mean * mean;
            const float rstd = rsqrtf(var + 1e-5f);
            float* yrow = yout + (size_t)r * 256;
            const float* prow = (LNV == 1) ? pos + (size_t)r * 256 : nullptr;
#pragma unroll
            for (int nt = 0; nt < 8; nt++) {
                const int col = wn * 64 + nt * 8 + t2;
                float o0 = (acc[mt][nt][rs * 2 + 0] - mean) * rstd * gam[col] + bet[col];
                float o1 = (acc[mt][nt][rs * 2 + 1] - mean) * rstd * gam[col + 1] + bet[col + 1];
                *(float2*)(yrow + col) = make_float2(o0, o1);
                if (LNV == 1) {
                    uint32_t* bp = (uint32_t*)(bout + (size_t)r * 256 + col);
                    *bp = pack_bf16(o0 + prow[col], o1 + prow[col + 1]);
                } else if (LNV == 2) {
                    uint32_t* bp = (uint32_t*)(bout + (size_t)r * 256 + col);
                    *bp = pack_bf16(o0, o1);
                }
            }
        }
    }
}

// ---------------- fused weight convert + bias concat ------------
struct WConvArgs {
    const float4* in[8];
    uint2* out[8];
    int off4[9];
    const float4* sob4;
    const float4* awb4;
    float4* bias384;
};
__global__ void wconv_kernel(WConvArgs a) {
    int i = blockIdx.x * blockDim.x + threadIdx.x;
    if (i < 96) {
        a.bias384[i] = (i < 64) ? a.sob4[i] : a.awb4[i - 64];
    }
    if (i >= a.off4[8]) return;
    int s = 0;
#pragma unroll
    for (int k = 1; k < 8; k++) s += (i >= a.off4[k]);
    int j = i - a.off4[s];
    float4 v = a.in[s][j];
    uint2 o;
    o.x = pack_bf16(v.x, v.y);
    o.y = pack_bf16(v.z, v.w);
    a.out[s][j] = o;
}

// ---------------- fp32 -> bf16 convert ----------------
__global__ void f2b_kernel(const float* __restrict__ in, __nv_bfloat16* __restrict__ out, int n4) {
    int i = blockIdx.x * blockDim.x + threadIdx.x;
    if (i < n4) {
        float4 v = ((const float4*)in)[i];
        uint2 o;
        o.x = pack_bf16(v.x, v.y);
        o.y = pack_bf16(v.z, v.w);
        ((uint2*)out)[i] = o;
    }
}

// ---------------- fused: qksum = bf16(tgt+pos), tgtb = bf16(tgt) ----------
__global__ void prep_kernel(const float* __restrict__ tgt, const float* __restrict__ pos,
                            __nv_bfloat16* __restrict__ qksum, __nv_bfloat16* __restrict__ tgtb,
                            int n4) {
    int i = blockIdx.x * blockDim.x + threadIdx.x;
    if (i < n4) {
        float4 x = ((const float4*)tgt)[i];
        float4 y = ((const float4*)pos)[i];
        uint2 t;
        t.x = pack_bf16(x.x, x.y);
        t.y = pack_bf16(x.z, x.w);
        ((uint2*)tgtb)[i] = t;
        uint2 o;
        o.x = pack_bf16(x.x + y.x, x.y + y.y);
        o.y = pack_bf16(x.z + y.z, x.w + y.w);
        ((uint2*)qksum)[i] = o;
    }
}

// ---------------- self-attention (lane = query), reduced registers ----------
__global__ __launch_bounds__(128, 5) void attn_kernel(
        const __nv_bfloat16* __restrict__ qk, const __nv_bfloat16* __restrict__ v,
        __nv_bfloat16* __restrict__ out) {
    const int seq  = blockIdx.x >> 1;
    const int w    = threadIdx.x >> 5;
    const int h    = ((blockIdx.x & 1) << 2) + w;
    const int lane = threadIdx.x & 31;

    __shared__ float Ks[4][25][32];
    __shared__ float Vs[4][25][32];
    __shared__ float Os[4][25][36];

    const size_t tokbase = (size_t)seq * TSEQ;
    for (int i = lane; i < TSEQ * 32; i += 32) {
        int r = i >> 5;
        Ks[w][r][lane] = __bfloat162float(qk[(tokbase + r) * 512 + 256 + h * 32 + lane]);
        Vs[w][r][lane] = __bfloat162float(v[(tokbase + r) * 256 + h * 32 + lane]);
    }
    __syncwarp();

    if (lane < TSEQ) {
        const uint4* qp = (const uint4*)(qk + (tokbase + lane) * 512 + h * 32);
        float p[25];
#pragma unroll
        for (int j = 0; j < TSEQ; j++) p[j] = 0.f;

#pragma unroll
        for (int ic = 0; ic < 4; ic++) {
            uint4 u = qp[ic];
            float qc[8];
            qc[0] = bf_lo(u.x); qc[1] = bf_hi(u.x);
            qc[2] = bf_lo(u.y); qc[3] = bf_hi(u.y);
            qc[4] = bf_lo(u.z); qc[5] = bf_hi(u.z);
            qc[6] = bf_lo(u.w); qc[7] = bf_hi(u.w);
#pragma unroll
            for (int j = 0; j < TSEQ; j++) {
                const float* kp = &Ks[w][j][ic * 8];
                float a = p[j];
#pragma unroll
                for (int i = 0; i < 8; i++) a = fmaf(qc[i], kp[i], a);
                p[j] = a;
            }
        }

        const float scale = 0.1767766952966369f;
        float m = -1e30f;
#pragma unroll
        for (int j = 0; j < TSEQ; j++) { p[j] *= scale; m = fmaxf(m, p[j]); }
        float sum = 0.f;
#pragma unroll
        for (int j = 0; j < TSEQ; j++) { p[j] = __expf(p[j] - m); sum += p[j]; }
        const float inv = 1.f / sum;
#pragma unroll
        for (int d4 = 0; d4 < 8; d4++) {
            float4 o = make_float4(0.f, 0.f, 0.f, 0.f);
#pragma unroll
            for (int j = 0; j < TSEQ; j++) {
                float4 v4 = ((const float4*)Vs[w][j])[d4];
                o.x = fmaf(p[j], v4.x, o.x); o.y = fmaf(p[j], v4.y, o.y);
                o.z = fmaf(p[j], v4.z, o.z); o.w = fmaf(p[j], v4.w, o.w);
            }
            float* orow = &Os[w][lane][d4 * 4];
            orow[0] = o.x * inv; orow[1] = o.y * inv;
            orow[2] = o.z * inv; orow[3] = o.w * inv;
        }
    }
    __syncwarp();
    for (int i = lane; i < TSEQ * 32; i += 32) {
        int r = i >> 5;
        out[(tokbase + r) * 256 + h * 32 + lane] = __float2bfloat16(Os[w][r][lane]);
    }
}

// ---------------- deformable sampling w/ fused aw softmax, bf16 value -------
__global__ __launch_bounds__(256) void deform_kernel(
        const float* __restrict__ ref,
        const int* __restrict__ shapes,
        const int* __restrict__ lstart,
        __nv_bfloat16* __restrict__ out) {
    const int token = blockIdx.x;
    const int h = threadIdx.x >> 5;
    const int lane = threadIdx.x & 31;
    const int b = token / LQTOT;
    const int lq = token - b * LQTOT;

    __shared__ float sAw[8][16];

    {
        float v = -1e30f;
        if (lane < 16) v = g_offaw[(size_t)token * 384 + 256 + h * 16 + lane];
        float m = v;
#pragma unroll
        for (int o = 8; o; o >>= 1) m = fmaxf(m, __shfl_xor_sync(~0u, m, o, 16));
        float e = (lane < 16) ? __expf(v - m) : 0.f;
        float s = e;
#pragma unroll
        for (int o = 8; o; o >>= 1) s += __shfl_xor_sync(~0u, s, o, 16);
        if (lane < 16) sAw[h][lane] = e / s;
    }
    __syncwarp();

    const float* offp = g_offaw + (size_t)token * 384 + h * 32;
    const float* awp  = sAw[h];
    const float* refp = ref + ((size_t)(b * LQTOT + lq) * NL) * 2;
    const size_t vbase = ((size_t)b * SVAL) * 256;

    float acc = 0.f;
#pragma unroll
    for (int l = 0; l < NL; l++) {
        const int Hl = shapes[l * 2];
        const int Wl = shapes[l * 2 + 1];
        const int st = lstart[l];
        const float rx = refp[l * 2];
        const float ry = refp[l * 2 + 1];
        const float fW = (float)Wl, fH = (float)Hl;
#pragma unroll
        for (int p = 0; p < 4; p++) {
            float ox = offp[l * 8 + p * 2];
            float oy = offp[l * 8 + p * 2 + 1];
            float aww = awp[l * 4 + p];
            float x = (rx + ox / fW) * fW - 0.5f;
            float y = (ry + oy / fH) * fH - 0.5f;
            float fx0 = floorf(x), fy0 = floorf(y);
            float wx = x - fx0, wy = y - fy0;
            int x0 = (int)fx0, y0 = (int)fy0;
            float tw[4] = {(1.f - wx) * (1.f - wy), wx * (1.f - wy),
                           (1.f - wx) * wy, wx * wy};
            int xs[4] = {x0, x0 + 1, x0, x0 + 1};
            int ys[4] = {y0, y0, y0 + 1, y0 + 1};
#pragma unroll
            for (int tgt = 0; tgt < 4; tgt++) {
                int xi = xs[tgt], yi = ys[tgt];
                if (xi >= 0 && xi < Wl && yi >= 0 && yi < Hl) {
                    size_t vi = vbase + ((size_t)(st + yi * Wl + xi)) * 256 + h * 32 + lane;
                    acc = fmaf(__bfloat162float(gb_value[vi]), tw[tgt] * aww, acc);
                }
            }
        }
    }
    out[(size_t)token * 256 + h * 32 + lane] = __float2bfloat16(acc);
}

// ---------------- launch ----------------
static void* sym(const void* s) {
    void* p = nullptr;
    cudaGetSymbolAddress(&p, s);
    return p;
}

template <int EPI, int OUTBF, int NC>
static void launch_gemm(const __nv_bfloat16* A, const __nv_bfloat16* B, const float* bias,
                        const float* res, void* C, int M, int N, cudaStream_t st) {
    static bool done = false;
    if (!done) {
        cudaFuncSetAttribute(gemm_mma<EPI, OUTBF, NC>, cudaFuncAttributeMaxDynamicSharedMemorySize, GEMM_SMEM);
        done = true;
    }
    dim3 grid(N / 128, (M + 127) / 128);
    gemm_mma<EPI, OUTBF, NC><<<grid, 256, GEMM_SMEM, st>>>(A, B, bias, res, C, M, N);
}

template <int LNV, int NC>
static void launch_gemm_ln(const __nv_bfloat16* A, const __nv_bfloat16* B, const float* bias,
                           const float* res, const float* gam, const float* bet,
                           const float* pos, float* yout, __nv_bfloat16* bout, int M) {
    static bool done = false;
    if (!done) {
        cudaFuncSetAttribute(gemm_ln<LNV, NC>, cudaFuncAttributeMaxDynamicSharedMemorySize, GEMM_LN_SMEM);
        done = true;
    }
    gemm_ln<LNV, NC><<<(M + 127) / 128, 512, GEMM_LN_SMEM>>>(A, B, bias, res, gam, bet, pos, yout, bout, M);
}

extern "C" void kernel_launch(void* const* d_in, const int* in_sizes, int n_in,
                              void* d_out, int out_size) {
    const float* tgt  = (const float*)d_in[0];
    const float* pos  = (const float*)d_in[1];
    const float* ref  = (const float*)d_in[2];
    const float* src  = (const float*)d_in[3];
    const int* shapes = (const int*)d_in[4];
    const int* lstart = (const int*)d_in[5];
    const float* in_proj_w  = (const float*)d_in[6];
    const float* in_proj_b  = (const float*)d_in[7];
    const float* out_proj_w = (const float*)d_in[8];
    const float* out_proj_b = (const float*)d_in[9];
    const float* ln1_g = (const float*)d_in[10];
    const float* ln1_b = (const float*)d_in[11];
    const float* samp_off_w = (const float*)d_in[12];
    const float* samp_off_b = (const float*)d_in[13];
    const float* aw_w = (const float*)d_in[14];
    const float* aw_b = (const float*)d_in[15];
    const float* vp_w = (const float*)d_in[16];
    const float* vp_b = (const float*)d_in[17];
    const float* op_w = (const float*)d_in[18];
    const float* op_b = (const float*)d_in[19];
    const float* ln2_g = (const float*)d_in[20];
    const float* ln2_b = (const float*)d_in[21];
    const float* ffn1_w = (const float*)d_in[22];
    const float* ffn1_b = (const float*)d_in[23];
    const float* ffn2_w = (const float*)d_in[24];
    const float* ffn2_b = (const float*)d_in[25];
    const float* ln3_g = (const float*)d_in[26];
    const float* ln3_b = (const float*)d_in[27];

    float* p_ln1   = (float*)sym(g_ln1);
    float* p_offaw = (float*)sym(g_offaw);
    float* p_ln2   = (float*)sym(g_ln2);
    float* p_b384  = (float*)sym(g_bias384);

    __nv_bfloat16* b_qk    = (__nv_bfloat16*)sym(gb_qk);
    __nv_bfloat16* b_v     = (__nv_bfloat16*)sym(gb_v);
    __nv_bfloat16* b_value = (__nv_bfloat16*)sym(gb_value);
    __nv_bfloat16* b_tgt   = (__nv_bfloat16*)sym(gb_tgt);
    __nv_bfloat16* b_qksum = (__nv_bfloat16*)sym(gb_qksum);
    __nv_bfloat16* b_attn  = (__nv_bfloat16*)sym(gb_attn);
    __nv_bfloat16* b_query = (__nv_bfloat16*)sym(gb_query);
    __nv_bfloat16* b_src   = (__nv_bfloat16*)sym(gb_src);
    __nv_bfloat16* b_accum = (__nv_bfloat16*)sym(gb_accum);
    __nv_bfloat16* b_ln2   = (__nv_bfloat16*)sym(gb_ln2);
    __nv_bfloat16* b_ffn1  = (__nv_bfloat16*)sym(gb_ffn1);
    __nv_bfloat16* b_inproj = (__nv_bfloat16*)sym(gb_inproj);
    __nv_bfloat16* b_outproj = (__nv_bfloat16*)sym(gb_outproj);
    __nv_bfloat16* b_soffaw = (__nv_bfloat16*)sym(gb_soffaw);
    __nv_bfloat16* b_vp    = (__nv_bfloat16*)sym(gb_vp);
    __nv_bfloat16* b_op    = (__nv_bfloat16*)sym(gb_op);
    __nv_bfloat16* b_f1w   = (__nv_bfloat16*)sym(gb_f1w);
    __nv_bfloat16* b_f2w   = (__nv_bfloat16*)sym(gb_f2w);

    static cudaStream_t s2 = nullptr, s3 = nullptr;
    static cudaEvent_t evRoot = nullptr, evW = nullptr, evPrep = nullptr, evV = nullptr, evVp = nullptr;
    if (!s2) {
        cudaStreamCreateWithFlags(&s2, cudaStreamNonBlocking);
        cudaStreamCreateWithFlags(&s3, cudaStreamNonBlocking);
        cudaEventCreateWithFlags(&evRoot, cudaEventDisableTiming);
        cudaEventCreateWithFlags(&evW, cudaEventDisableTiming);
        cudaEventCreateWithFlags(&evPrep, cudaEventDisableTiming);
        cudaEventCreateWithFlags(&evV, cudaEventDisableTiming);
        cudaEventCreateWithFlags(&evVp, cudaEventDisableTiming);
    }

    // Fork side streams from the capturing stream.
    cudaEventRecord(evRoot, 0);
    cudaStreamWaitEvent(s2, evRoot, 0);
    cudaStreamWaitEvent(s3, evRoot, 0);

    // s2: weight converts + bias concat
    {
        WConvArgs a;
        const float* ins[8] = {in_proj_w, out_proj_w, samp_off_w, aw_w, vp_w, op_w, ffn1_w, ffn2_w};
        __nv_bfloat16* outs[8] = {b_inproj, b_outproj, b_soffaw, b_soffaw + 256 * 256,
                                  b_vp, b_op, b_f1w, b_f2w};
        int ns[8] = {768 * 256, 256 * 256, 256 * 256, 128 * 256, 256 * 256, 256 * 256, 1024 * 256, 256 * 1024};
        int acc4 = 0;
        for (int i = 0; i < 8; i++) {
            a.in[i] = (const float4*)ins[i];
            a.out[i] = (uint2*)outs[i];
            a.off4[i] = acc4;
            acc4 += ns[i] / 4;
        }
        a.off4[8] = acc4;
        a.sob4 = (const float4*)samp_off_b;
        a.awb4 = (const float4*)aw_b;
        a.bias384 = (float4*)p_b384;
        wconv_kernel<<<(acc4 + 255) / 256, 256, 0, s2>>>(a);
        cudaEventRecord(evW, s2);
    }
    // main: prep (tgt+pos)
    const int n4 = NTOK * CDIM / 4;
    prep_kernel<<<(n4 + 255) / 256, 256>>>(tgt, pos, b_qksum, b_tgt, n4);
    cudaEventRecord(evPrep, 0);
    // s3: src convert
    const int s4 = BB * SVAL * CDIM / 4;
    f2b_kernel<<<(s4 + 255) / 256, 256, 0, s3>>>(src, b_src, s4);

    // main: qk GEMM
    cudaStreamWaitEvent(0, evW, 0);
    launch_gemm<0, 1, 4>(b_qksum, b_inproj, in_proj_b, nullptr, b_qk, NTOK, 512, 0);

    // s2: v GEMM
    cudaStreamWaitEvent(s2, evPrep, 0);
    launch_gemm<0, 1, 4>(b_tgt, b_inproj + 512 * 256, in_proj_b + 512, nullptr, b_v, NTOK, 256, s2);
    cudaEventRecord(evV, s2);

    // s3: vp GEMM
    cudaStreamWaitEvent(s3, evW, 0);
    launch_gemm<0, 1, 4>(b_src, b_vp, vp_b, nullptr, b_value, BB * SVAL, 256, s3);
    cudaEventRecord(evVp, s3);

    cudaStreamWaitEvent(0, evV, 0);
    attn_kernel<<<NSEQ * 2, 128>>>(b_qk, b_v, b_attn);

    // outproj + residual(tgt) + LN1 fused (emits ln1 fp32 + query bf16 = ln1+pos)
    launch_gemm_ln<1, 4>(b_attn, b_outproj, out_proj_b, tgt, ln1_g, ln1_b, pos,
                         p_ln1, b_query, NTOK);

    launch_gemm<0, 0, 4>(b_query, b_soffaw, p_b384, nullptr, p_offaw, NTOK, 384, 0);

    cudaStreamWaitEvent(0, evVp, 0);
    deform_kernel<<<NTOK, 256>>>(ref, shapes, lstart, b_accum);

    // op + residual(ln1) + LN2 fused (emits ln2 fp32 + ln2 bf16)
    launch_gemm_ln<2, 4>(b_accum, b_op, op_b, p_ln1, ln2_g, ln2_b, nullptr,
                         p_ln2, b_ln2, NTOK);

    launch_gemm<1, 1, 4>(b_ln2, b_f1w, ffn1_b, nullptr, b_ffn1, NTOK, DFF, 0);

    // ffn2 + residual(ln2) + LN3 fused -> final output
    launch_gemm_ln<3, 16>(b_ffn1, b_f2w, ffn2_b, p_ln2, ln3_g, ln3_b, nullptr,
                          (float*)d_out, nullptr, NTOK);
}